// round 3
// baseline (speedup 1.0000x reference)
#include <cuda_runtime.h>
#include <cuda_bf16.h>
#include <math.h>

#define NN 100000
#define EE 1600000
#define HH 128
#define CC 10
#define EPS 1e-5f

// ---------------- static device scratch (no allocations allowed) ----------------
__device__ float g_hw[(size_t)NN * HH];   // GEMM output (pre-aggregation)
__device__ float g_t [(size_t)NN * HH];   // layer activation (post relu)
__device__ float g_deg [NN];
__device__ float g_dinv[NN];
__device__ float g_S   [NN];              // sum of incoming norms (incl self loop)
__device__ int   g_cnt [NN];
__device__ int   g_rowptr[NN + 1];
__device__ int   g_next[NN];
__device__ int   g_srcs[EE];
__device__ float g_wn  [EE];
__device__ float g_sum[HH];
__device__ float g_sq [HH];
__device__ float g_Wf [HH * HH];
__device__ float g_bf [HH];
__device__ float g_cw [HH];               // BN-fold constant, propagated via S_n
__device__ float g_Wlf[HH * CC];
__device__ float g_blf[CC];

// ---------------- init: deg=1 (self loop), cnt=0, stats=0, cw=0 ----------------
__global__ void k_init() {
    int i = blockIdx.x * blockDim.x + threadIdx.x;
    if (i < NN) { g_deg[i] = 1.0f; g_cnt[i] = 0; }
    if (i < HH) { g_sum[i] = 0.f; g_sq[i] = 0.f; g_cw[i] = 0.f; }
}

// ---------------- histogram: weighted degree + in-degree counts ----------------
__global__ void k_count(const int* __restrict__ ei, const float* __restrict__ ew) {
    int e = blockIdx.x * blockDim.x + threadIdx.x;
    if (e >= EE) return;
    int c = ei[EE + e];
    atomicAdd(&g_deg[c], ew[e]);
    atomicAdd(&g_cnt[c], 1);
}

// ---------------- single-block exclusive scan -> rowptr, next; also dinv ----------------
__global__ void k_scan() {
    __shared__ int ssum[1024];
    const int tid = threadIdx.x;
    const int CH = (NN + 1023) / 1024;   // 98
    int beg = tid * CH;
    int end = beg + CH; if (end > NN) end = NN;
    if (beg > NN) beg = NN;

    int s = 0;
    for (int i = beg; i < end; i++) s += g_cnt[i];
    ssum[tid] = s;
    __syncthreads();
    for (int off = 1; off < 1024; off <<= 1) {
        int v = (tid >= off) ? ssum[tid - off] : 0;
        __syncthreads();
        ssum[tid] += v;
        __syncthreads();
    }
    int ex = (tid == 0) ? 0 : ssum[tid - 1];
    for (int i = beg; i < end; i++) {
        g_rowptr[i] = ex;
        g_next[i]   = ex;
        ex += g_cnt[i];
        g_dinv[i] = rsqrtf(g_deg[i]);   // deg >= 1 always (self loop)
    }
    if (tid == 1023) g_rowptr[NN] = ssum[1023];
}

// ---------------- scatter edges into CSR (by destination) ----------------
__global__ void k_scatter(const int* __restrict__ ei, const float* __restrict__ ew) {
    int e = blockIdx.x * blockDim.x + threadIdx.x;
    if (e >= EE) return;
    int r = ei[e];
    int c = ei[EE + e];
    int pos = atomicAdd(&g_next[c], 1);
    g_srcs[pos] = r;
    g_wn[pos]   = g_dinv[r] * ew[e] * g_dinv[c];
}

// ---------------- per-node sum of incoming norms: S_n = dinv^2 + sum(wn) ----------------
__global__ void __launch_bounds__(256) k_ssum() {
    const int lane   = threadIdx.x & 31;
    const int gwarp  = (blockIdx.x * blockDim.x + threadIdx.x) >> 5;
    const int nwarp  = (gridDim.x * blockDim.x) >> 5;
    for (int node = gwarp; node < NN; node += nwarp) {
        int s = g_rowptr[node], e = g_rowptr[node + 1];
        float acc = 0.f;
        for (int i = s + lane; i < e; i += 32) acc += g_wn[i];
#pragma unroll
        for (int off = 16; off; off >>= 1) acc += __shfl_xor_sync(0xffffffffu, acc, off);
        if (lane == 0) { float d = g_dinv[node]; g_S[node] = acc + d * d; }
    }
}

// ---------------- fp32 GEMM: C[N,128] = A[N,128] @ W[128,128] ----------------
// 256 thr: 8 warps x 8 rows (64 rows/block), 32 col-groups of 4.
// A loads warp-uniform (broadcast), W loads coalesced; both L1-resident.
__global__ void __launch_bounds__(256) k_gemm(const float* __restrict__ A,
                                              const float* __restrict__ W,
                                              float* __restrict__ Cv) {
    const int c4 = (threadIdx.x & 31) * 4;
    const int r0 = blockIdx.x * 64 + (threadIdx.x >> 5) * 8;

    const float* arow[8];
#pragma unroll
    for (int r = 0; r < 8; r++) {
        int row = r0 + r; if (row >= NN) row = NN - 1;
        arow[r] = A + (size_t)row * HH;
    }

    float4 acc[8];
#pragma unroll
    for (int r = 0; r < 8; r++) acc[r] = make_float4(0.f, 0.f, 0.f, 0.f);

    for (int kk = 0; kk < HH; kk += 4) {
        float4 w0 = *(const float4*)&W[(kk + 0) * HH + c4];
        float4 w1 = *(const float4*)&W[(kk + 1) * HH + c4];
        float4 w2 = *(const float4*)&W[(kk + 2) * HH + c4];
        float4 w3 = *(const float4*)&W[(kk + 3) * HH + c4];
#pragma unroll
        for (int r = 0; r < 8; r++) {
            float4 a = *(const float4*)(arow[r] + kk);
            acc[r].x += a.x * w0.x + a.y * w1.x + a.z * w2.x + a.w * w3.x;
            acc[r].y += a.x * w0.y + a.y * w1.y + a.z * w2.y + a.w * w3.y;
            acc[r].z += a.x * w0.z + a.y * w1.z + a.z * w2.z + a.w * w3.z;
            acc[r].w += a.x * w0.w + a.y * w1.w + a.z * w2.w + a.w * w3.w;
        }
    }
#pragma unroll
    for (int r = 0; r < 8; r++) {
        int row = r0 + r;
        if (row < NN) *(float4*)&Cv[(size_t)row * HH + c4] = acc[r];
    }
}

// ---------------- aggregation: t[n] = relu(agg + b + S_n*cw) + fused BN stats ----------------
__global__ void __launch_bounds__(256) k_agg(const float* __restrict__ hw,
                                             const float* __restrict__ bias,
                                             const float* __restrict__ cw) {
    const int lane  = threadIdx.x & 31;
    const int wid   = threadIdx.x >> 5;
    const int gwarp = blockIdx.x * 8 + wid;
    const int nwarp = gridDim.x * 8;

    float4 bv  = ((const float4*)bias)[lane];
    float4 cwv = ((const float4*)cw)[lane];
    float4 ls = make_float4(0.f, 0.f, 0.f, 0.f);
    float4 lq = make_float4(0.f, 0.f, 0.f, 0.f);

    for (int n = gwarp; n < NN; n += nwarp) {
        float S  = g_S[n];          // hoisted: overlaps with gather chain
        float di = g_dinv[n];
        float sn = di * di;
        float4 v = ((const float4*)(hw + (size_t)n * HH))[lane];
        float4 acc = make_float4(sn * v.x, sn * v.y, sn * v.z, sn * v.w);

        int s = g_rowptr[n], e = g_rowptr[n + 1];
        for (int base = s; base < e; base += 32) {
            int idx = base + lane;
            int   src = 0; float w = 0.f;
            if (idx < e) { src = g_srcs[idx]; w = g_wn[idx]; }
            int cnt = e - base; if (cnt > 32) cnt = 32;
            for (int k = 0; k < cnt; k++) {
                int   ss = __shfl_sync(0xffffffffu, src, k);
                float ww = __shfl_sync(0xffffffffu, w,   k);
                float4 hv = ((const float4*)(hw + (size_t)ss * HH))[lane];
                acc.x += ww * hv.x; acc.y += ww * hv.y;
                acc.z += ww * hv.z; acc.w += ww * hv.w;
            }
        }
        float4 r;
        r.x = fmaxf(acc.x + bv.x + S * cwv.x, 0.f);
        r.y = fmaxf(acc.y + bv.y + S * cwv.y, 0.f);
        r.z = fmaxf(acc.z + bv.z + S * cwv.z, 0.f);
        r.w = fmaxf(acc.w + bv.w + S * cwv.w, 0.f);
        ((float4*)(g_t + (size_t)n * HH))[lane] = r;
        ls.x += r.x; ls.y += r.y; ls.z += r.z; ls.w += r.w;
        lq.x += r.x * r.x; lq.y += r.y * r.y; lq.z += r.z * r.z; lq.w += r.w * r.w;
    }

    __shared__ float s_sum[HH], s_sq[HH];
    if (threadIdx.x < HH) { s_sum[threadIdx.x] = 0.f; s_sq[threadIdx.x] = 0.f; }
    __syncthreads();
    atomicAdd(&s_sum[lane * 4 + 0], ls.x); atomicAdd(&s_sq[lane * 4 + 0], lq.x);
    atomicAdd(&s_sum[lane * 4 + 1], ls.y); atomicAdd(&s_sq[lane * 4 + 1], lq.y);
    atomicAdd(&s_sum[lane * 4 + 2], ls.z); atomicAdd(&s_sq[lane * 4 + 2], lq.z);
    atomicAdd(&s_sum[lane * 4 + 3], ls.w); atomicAdd(&s_sq[lane * 4 + 3], lq.w);
    __syncthreads();
    if (threadIdx.x < HH) {
        atomicAdd(&g_sum[threadIdx.x], s_sum[threadIdx.x]);
        atomicAdd(&g_sq [threadIdx.x], s_sq [threadIdx.x]);
    }
}

// ---------------- fold BatchNorm into next layer's weights; zero stats ----------------
// BN(h)@W = h @ (diag(a)W) + c^T W ;  a = gamma*rsqrt(var+eps), c = beta - a*mean
// head==0 (propagating layer): Wf = diag(a)W, cw = c^T W (scaled by S_n later), bf = b
// head==1 (output head):       bf = b + c^T W directly
__global__ void k_fold(const float* __restrict__ W, const float* __restrict__ b,
                       const float* __restrict__ gamma, const float* __restrict__ beta,
                       float* __restrict__ Wf, float* __restrict__ bf,
                       float* __restrict__ cw, int outdim, int head) {
    __shared__ float sa[HH], sc[HH];
    int j = threadIdx.x;   // 128 threads
    float mean = g_sum[j] * (1.0f / NN);
    float var  = g_sq [j] * (1.0f / NN) - mean * mean;
    float a = gamma[j] * rsqrtf(var + EPS);
    sa[j] = a;
    sc[j] = beta[j] - a * mean;
    __syncthreads();
    if (j < outdim) {
        float acc = 0.f;
        for (int jj = 0; jj < HH; jj++) {
            float wv = W[jj * outdim + j];
            Wf[jj * outdim + j] = sa[jj] * wv;
            acc += sc[jj] * wv;
        }
        if (head) {
            bf[j] = b[j] + acc;
        } else {
            bf[j] = b[j];
            cw[j] = acc;
        }
    }
    g_sum[j] = 0.f;
    g_sq [j] = 0.f;
}

// ---------------- final: out[N,10] = t @ Wlf + blf ----------------
__global__ void __launch_bounds__(256) k_final(const float* __restrict__ t,
                                               float* __restrict__ out) {
    __shared__ float sW[HH * CC];
    __shared__ float sb[CC];
    for (int i = threadIdx.x; i < HH * CC; i += blockDim.x) sW[i] = g_Wlf[i];
    if (threadIdx.x < CC) sb[threadIdx.x] = g_blf[threadIdx.x];
    __syncthreads();

    int lane = threadIdx.x & 31;
    int n = blockIdx.x * 8 + (threadIdx.x >> 5);
    if (n >= NN) return;
    float4 t4 = ((const float4*)(t + (size_t)n * HH))[lane];
    float p[CC];
#pragma unroll
    for (int c = 0; c < CC; c++) {
        const float* wr = &sW[(4 * lane) * CC + c];
        p[c] = t4.x * wr[0] + t4.y * wr[CC] + t4.z * wr[2 * CC] + t4.w * wr[3 * CC];
    }
#pragma unroll
    for (int off = 16; off; off >>= 1)
#pragma unroll
        for (int c = 0; c < CC; c++) p[c] += __shfl_xor_sync(0xffffffffu, p[c], off);
    if (lane < CC) out[(size_t)n * CC + lane] = p[lane] + sb[lane];
}

// ---------------- host launcher ----------------
extern "C" void kernel_launch(void* const* d_in, const int* in_sizes, int n_in,
                              void* d_out, int out_size) {
    const float* x  = (const float*)d_in[0];
    const int*   ei = (const int*)d_in[1];
    const float* ew = (const float*)d_in[2];

    const float *W1,*b1,*W2,*b2,*W3,*b3,*g1,*be1,*g2,*be2,*g3,*be3,*Wl,*bl;
    if (in_sizes[5] == HH * HH) {   // dict order: W1,b1,W2,b2,W3,b3,g1,be1,...
        W1=(const float*)d_in[3];  b1=(const float*)d_in[4];
        W2=(const float*)d_in[5];  b2=(const float*)d_in[6];
        W3=(const float*)d_in[7];  b3=(const float*)d_in[8];
        g1=(const float*)d_in[9];  be1=(const float*)d_in[10];
        g2=(const float*)d_in[11]; be2=(const float*)d_in[12];
        g3=(const float*)d_in[13]; be3=(const float*)d_in[14];
        Wl=(const float*)d_in[15]; bl=(const float*)d_in[16];
    } else {                         // signature order: W1,b1,g1,be1,W2,...
        W1=(const float*)d_in[3];  b1=(const float*)d_in[4];
        g1=(const float*)d_in[5];  be1=(const float*)d_in[6];
        W2=(const float*)d_in[7];  b2=(const float*)d_in[8];
        g2=(const float*)d_in[9];  be2=(const float*)d_in[10];
        W3=(const float*)d_in[11]; b3=(const float*)d_in[12];
        g3=(const float*)d_in[13]; be3=(const float*)d_in[14];
        Wl=(const float*)d_in[15]; bl=(const float*)d_in[16];
    }

    float* out = (float*)d_out;

    float *hw, *tt, *Wf, *bf, *cw, *Wlf, *blf;
    cudaGetSymbolAddress((void**)&hw,  g_hw);
    cudaGetSymbolAddress((void**)&tt,  g_t);
    cudaGetSymbolAddress((void**)&Wf,  g_Wf);
    cudaGetSymbolAddress((void**)&bf,  g_bf);
    cudaGetSymbolAddress((void**)&cw,  g_cw);
    cudaGetSymbolAddress((void**)&Wlf, g_Wlf);
    cudaGetSymbolAddress((void**)&blf, g_blf);

    const int TB = 256;
    const int gN  = (NN + TB - 1) / TB;
    const int gE  = (EE + TB - 1) / TB;
    const int gGE = (NN + 63) / 64;             // gemm: 64 rows per block
    const int gAG = 1184;                       // persistent agg: ~8 blocks/SM
    const int gFN = (NN + 7) / 8;               // final: 8 nodes per block

    // graph normalization + CSR build
    k_init   <<<gN, TB>>>();
    k_count  <<<gE, TB>>>(ei, ew);
    k_scan   <<<1, 1024>>>();
    k_scatter<<<gE, TB>>>(ei, ew);
    k_ssum   <<<gAG, TB>>>();

    // layer 1 (no BN fold; cw is zero)
    k_gemm<<<gGE, TB>>>(x, W1, hw);
    k_agg <<<gAG, TB>>>(hw, b1, cw);
    // layer 2 (BN1 folded into W2; constant propagated via S_n)
    k_fold<<<1, HH>>>(W2, b2, g1, be1, Wf, bf, cw, HH, 0);
    k_gemm<<<gGE, TB>>>(tt, Wf, hw);
    k_agg <<<gAG, TB>>>(hw, bf, cw);
    // layer 3 (BN2 folded into W3)
    k_fold<<<1, HH>>>(W3, b3, g2, be2, Wf, bf, cw, HH, 0);
    k_gemm<<<gGE, TB>>>(tt, Wf, hw);
    k_agg <<<gAG, TB>>>(hw, bf, cw);
    // output head (BN3 folded into Wl; no propagation)
    k_fold <<<1, HH>>>(Wl, bl, g3, be3, Wlf, blf, blf, CC, 1);
    k_final<<<gFN, TB>>>(tt, out);
}